// round 15
// baseline (speedup 1.0000x reference)
#include <cuda_runtime.h>

// CAN co-action unit: per-sample 2-layer MLP, D=16, N=50, B=16384.
// R13 core (warp-autonomous, FFMA2, broadcast LDS.128 weights, strided x
// LDG.128, fire-and-forget STG.128) with full lane utilization: work unit is
// the same-sample row pair (j, j+25), assigned globally so every warp has 32
// active lanes (was 25/32). A warp's 32 pairs span <=3 samples; the warp
// stages every slab it reads itself (duplicate STS across warps is benign,
// same data), __syncwarp only. Slabs padded to 552 words so the <=3 distinct
// broadcast addresses of each weight LDS.128 are bank-disjoint (1 wavefront).
// R14 fix: a CTA's 256 pairs can span 12 samples (NSLAB 11 -> 12).

#define D 16
#define N 50
#define PARAMS 544            // 2*(256+16) words
#define PSTRIDE 552           // padded slab stride, words (%32==8)
#define THREADS 256           // 8 warps; CTA covers 256 pairs
#define NSLAB 12              // max distinct samples per CTA (256/25 spans <=12)
#define PAIRS_PER_SAMPLE 25   // N/2

__device__ __forceinline__ unsigned long long splat2(float x) {
    unsigned long long r; unsigned u = __float_as_uint(x);
    asm("mov.b64 %0, {%1, %1};" : "=l"(r) : "r"(u));
    return r;
}
__device__ __forceinline__ void ffma2(unsigned long long& d,
                                      unsigned long long a, unsigned long long b) {
    asm("fma.rn.f32x2 %0, %1, %2, %0;" : "+l"(d) : "l"(a), "l"(b));
}
__device__ __forceinline__ void unpack2(unsigned long long v, float& lo, float& hi) {
    unsigned a, b;
    asm("mov.b64 {%0, %1}, %2;" : "=r"(a), "=r"(b) : "l"(v));
    lo = __uint_as_float(a); hi = __uint_as_float(b);
}

__global__ __launch_bounds__(THREADS, 3) void can_kernel(
    const float* __restrict__ user_emb,
    const float* __restrict__ item_emb,
    float* __restrict__ out)
{
    __shared__ float sp[NSLAB * PSTRIDE];   // padded slabs for CTA's samples

    const int t = threadIdx.x;
    const int w = t >> 5;
    const int l = t & 31;

    const int cta_pair0 = blockIdx.x * THREADS;
    const int base_s    = cta_pair0 / PAIRS_PER_SAMPLE;

    // ---- Warp stages every slab its 32 pairs read (<=3 samples), coalesced.
    {
        const int pw   = cta_pair0 + 32 * w;
        const int s_lo = pw / PAIRS_PER_SAMPLE;
        const int s_hi = (pw + 31) / PAIRS_PER_SAMPLE;
        for (int s = s_lo; s <= s_hi; s++) {
            float* slab = sp + (s - base_s) * PSTRIDE;
            const float4* src = (const float4*)(item_emb + (size_t)s * PARAMS);
            #pragma unroll
            for (int k = 0; k < 5; k++) {
                int i = l + 32 * k;
                if (i < PARAMS / 4)
                    ((float4*)slab)[i] = src[i];
            }
        }
    }

    // ---- This lane's pair: sample s, rows s*50+j and s*50+j+25.
    const int P = cta_pair0 + t;
    const int s = P / PAIRS_PER_SAMPLE;
    const int j = P - s * PAIRS_PER_SAMPLE;
    const size_t grow = (size_t)s * N + j;

    float x0[D], x1[D];
    {
        const float4* r0 = (const float4*)(user_emb + grow * D);
        const float4* r1 = (const float4*)(user_emb + (grow + 25) * D);
        #pragma unroll
        for (int q = 0; q < 4; q++) {
            float4 a = r0[q], b = r1[q];
            x0[q*4+0]=a.x; x0[q*4+1]=a.y; x0[q*4+2]=a.z; x0[q*4+3]=a.w;
            x1[q*4+0]=b.x; x1[q*4+1]=b.y; x1[q*4+2]=b.z; x1[q*4+3]=b.w;
        }
    }

    __syncwarp();   // warp wrote every slab word it reads

    const float* p = sp + (s - base_s) * PSTRIDE;
    unsigned long long a0[8], a1[8];

    // ---- Layer 1: relu(x W0 + b0).  W0 = p[0..255], b0 = p[256..271].
    {
        const ulonglong2* bp = (const ulonglong2*)(p + 256);
        #pragma unroll
        for (int h = 0; h < 4; h++) {
            ulonglong2 bv = bp[h];
            a0[2*h]=bv.x; a0[2*h+1]=bv.y;
            a1[2*h]=bv.x; a1[2*h+1]=bv.y;
        }
        #pragma unroll
        for (int d = 0; d < D; d++) {
            const ulonglong2* wr = (const ulonglong2*)(p + d * D);
            ulonglong2 wA = wr[0], wB = wr[1], wC = wr[2], wE = wr[3];
            unsigned long long u0 = splat2(x0[d]), u1 = splat2(x1[d]);
            ffma2(a0[0],u0,wA.x); ffma2(a1[0],u1,wA.x);
            ffma2(a0[1],u0,wA.y); ffma2(a1[1],u1,wA.y);
            ffma2(a0[2],u0,wB.x); ffma2(a1[2],u1,wB.x);
            ffma2(a0[3],u0,wB.y); ffma2(a1[3],u1,wB.y);
            ffma2(a0[4],u0,wC.x); ffma2(a1[4],u1,wC.x);
            ffma2(a0[5],u0,wC.y); ffma2(a1[5],u1,wC.y);
            ffma2(a0[6],u0,wE.x); ffma2(a1[6],u1,wE.x);
            ffma2(a0[7],u0,wE.y); ffma2(a1[7],u1,wE.y);
        }
        #pragma unroll
        for (int h = 0; h < 8; h++) {
            float lo, hi;
            unpack2(a0[h], lo, hi);
            x0[2*h] = fmaxf(lo, 0.0f); x0[2*h+1] = fmaxf(hi, 0.0f);
            unpack2(a1[h], lo, hi);
            x1[2*h] = fmaxf(lo, 0.0f); x1[2*h+1] = fmaxf(hi, 0.0f);
        }
    }

    // ---- Layer 2: x W1 + b1.  W1 = p[272..527], b1 = p[528..543].
    {
        const ulonglong2* bp = (const ulonglong2*)(p + 528);
        #pragma unroll
        for (int h = 0; h < 4; h++) {
            ulonglong2 bv = bp[h];
            a0[2*h]=bv.x; a0[2*h+1]=bv.y;
            a1[2*h]=bv.x; a1[2*h+1]=bv.y;
        }
        #pragma unroll
        for (int d = 0; d < D; d++) {
            const ulonglong2* wr = (const ulonglong2*)(p + 272 + d * D);
            ulonglong2 wA = wr[0], wB = wr[1], wC = wr[2], wE = wr[3];
            unsigned long long u0 = splat2(x0[d]), u1 = splat2(x1[d]);
            ffma2(a0[0],u0,wA.x); ffma2(a1[0],u1,wA.x);
            ffma2(a0[1],u0,wA.y); ffma2(a1[1],u1,wA.y);
            ffma2(a0[2],u0,wB.x); ffma2(a1[2],u1,wB.x);
            ffma2(a0[3],u0,wB.y); ffma2(a1[3],u1,wB.y);
            ffma2(a0[4],u0,wC.x); ffma2(a1[4],u1,wC.x);
            ffma2(a0[5],u0,wC.y); ffma2(a1[5],u1,wC.y);
            ffma2(a0[6],u0,wE.x); ffma2(a1[6],u1,wE.x);
            ffma2(a0[7],u0,wE.y); ffma2(a1[7],u1,wE.y);
        }
    }

    // ---- Relu + store both rows (4x STG.128 each, fire-and-forget).
    {
        float4* o0 = (float4*)(out + grow * D);
        float4* o1 = (float4*)(out + (grow + 25) * D);
        #pragma unroll
        for (int q = 0; q < 4; q++) {
            float l0,h0,l1,h1, l2,h2,l3,h3;
            unpack2(a0[2*q],   l0, h0); unpack2(a0[2*q+1], l1, h1);
            unpack2(a1[2*q],   l2, h2); unpack2(a1[2*q+1], l3, h3);
            float4 v0 = { fmaxf(l0,0.f), fmaxf(h0,0.f), fmaxf(l1,0.f), fmaxf(h1,0.f) };
            float4 v1 = { fmaxf(l2,0.f), fmaxf(h2,0.f), fmaxf(l3,0.f), fmaxf(h3,0.f) };
            o0[q] = v0;
            o1[q] = v1;
        }
    }
}

extern "C" void kernel_launch(void* const* d_in, const int* in_sizes, int n_in,
                              void* d_out, int out_size) {
    const float* user_emb = (const float*)d_in[0];
    const float* item_emb = (const float*)d_in[1];
    float* out = (float*)d_out;
    const int B = in_sizes[1] / PARAMS;                 // 16384
    const int pairs = B * PAIRS_PER_SAMPLE;             // 409600
    can_kernel<<<pairs / THREADS, THREADS>>>(user_emb, item_emb, out);
}

// round 16
// speedup vs baseline: 1.1331x; 1.1331x over previous
#include <cuda_runtime.h>

// CAN co-action unit: per-sample 2-layer MLP, D=16, N=50, B=16384.
// Champion structure (R12+R13): warp-autonomous, 1 warp = 1 sample.
//  - lanes 0..24 own 2 same-sample rows (j, j+25) in registers end-to-end
//  - warp stages its own 544-word param slab (coalesced LDG.128 -> STS.128),
//    __syncwarp only - no CTA barrier anywhere (R12 win: decorrelated DRAM)
//  - weights read as broadcast LDS.128 from the warp-private slab
//  - packed fma.rn.f32x2 compute (R13 win: halved FFMA issue)
//  - fire-and-forget STG.128 stores
// R16 tweak: x-row LDG.128 issued FIRST, so their DRAM latency is covered by
// the staging sequence + syncwarp in addition to the layer-1 bias setup.

#define D 16
#define N 50
#define PARAMS 544            // 2*(256+16) words; 2176B
#define WPC 8                 // warps (=samples) per CTA
#define THREADS (WPC * 32)    // 256
#define CTA_ROWS (WPC * N)    // 400

__device__ __forceinline__ unsigned long long splat2(float x) {
    unsigned long long r; unsigned u = __float_as_uint(x);
    asm("mov.b64 %0, {%1, %1};" : "=l"(r) : "r"(u));
    return r;
}
__device__ __forceinline__ void ffma2(unsigned long long& d,
                                      unsigned long long a, unsigned long long b) {
    asm("fma.rn.f32x2 %0, %1, %2, %0;" : "+l"(d) : "l"(a), "l"(b));
}
__device__ __forceinline__ void unpack2(unsigned long long v, float& lo, float& hi) {
    unsigned a, b;
    asm("mov.b64 {%0, %1}, %2;" : "=r"(a), "=r"(b) : "l"(v));
    lo = __uint_as_float(a); hi = __uint_as_float(b);
}

__global__ __launch_bounds__(THREADS, 3) void can_kernel(
    const float* __restrict__ user_emb,
    const float* __restrict__ item_emb,
    float* __restrict__ out)
{
    __shared__ float sp[WPC * PARAMS];   // warp-private slabs, uniform reads

    const int t = threadIdx.x;
    const int w = t >> 5;
    const int l = t & 31;

    // ---- Issue this lane's x-row loads FIRST (longest-latency ops).
    const bool active = (l < 25);
    const size_t grow = (size_t)blockIdx.x * CTA_ROWS + w * N + l;
    float x0[D], x1[D];
    if (active) {
        const float4* r0 = (const float4*)(user_emb + grow * D);
        const float4* r1 = (const float4*)(user_emb + (grow + 25) * D);
        #pragma unroll
        for (int q = 0; q < 4; q++) {
            float4 a = r0[q], b = r1[q];
            x0[q*4+0]=a.x; x0[q*4+1]=a.y; x0[q*4+2]=a.z; x0[q*4+3]=a.w;
            x1[q*4+0]=b.x; x1[q*4+1]=b.y; x1[q*4+2]=b.z; x1[q*4+3]=b.w;
        }
    }

    // ---- Warp stages its own sample's params: 136 float4, coalesced.
    float* slab = sp + w * PARAMS;
    {
        const float4* src = (const float4*)(item_emb
                            + ((size_t)blockIdx.x * WPC + w) * PARAMS);
        #pragma unroll
        for (int k = 0; k < 5; k++) {
            int i = l + 32 * k;
            if (i < PARAMS / 4)
                ((float4*)slab)[i] = src[i];
        }
    }

    __syncwarp();                        // warp-local visibility only

    if (!active) return;

    const float* p = slab;
    unsigned long long a0[8], a1[8];

    // ---- Layer 1: relu(x W0 + b0).  W0 = p[0..255], b0 = p[256..271].
    {
        const ulonglong2* bp = (const ulonglong2*)(p + 256);
        #pragma unroll
        for (int h = 0; h < 4; h++) {
            ulonglong2 bv = bp[h];
            a0[2*h]=bv.x; a0[2*h+1]=bv.y;
            a1[2*h]=bv.x; a1[2*h+1]=bv.y;
        }
        #pragma unroll
        for (int d = 0; d < D; d++) {
            const ulonglong2* wr = (const ulonglong2*)(p + d * D);
            ulonglong2 wA = wr[0], wB = wr[1], wC = wr[2], wE = wr[3];
            unsigned long long u0 = splat2(x0[d]), u1 = splat2(x1[d]);
            ffma2(a0[0],u0,wA.x); ffma2(a1[0],u1,wA.x);
            ffma2(a0[1],u0,wA.y); ffma2(a1[1],u1,wA.y);
            ffma2(a0[2],u0,wB.x); ffma2(a1[2],u1,wB.x);
            ffma2(a0[3],u0,wB.y); ffma2(a1[3],u1,wB.y);
            ffma2(a0[4],u0,wC.x); ffma2(a1[4],u1,wC.x);
            ffma2(a0[5],u0,wC.y); ffma2(a1[5],u1,wC.y);
            ffma2(a0[6],u0,wE.x); ffma2(a1[6],u1,wE.x);
            ffma2(a0[7],u0,wE.y); ffma2(a1[7],u1,wE.y);
        }
        #pragma unroll
        for (int h = 0; h < 8; h++) {
            float lo, hi;
            unpack2(a0[h], lo, hi);
            x0[2*h] = fmaxf(lo, 0.0f); x0[2*h+1] = fmaxf(hi, 0.0f);
            unpack2(a1[h], lo, hi);
            x1[2*h] = fmaxf(lo, 0.0f); x1[2*h+1] = fmaxf(hi, 0.0f);
        }
    }

    // ---- Layer 2: x W1 + b1.  W1 = p[272..527], b1 = p[528..543].
    {
        const ulonglong2* bp = (const ulonglong2*)(p + 528);
        #pragma unroll
        for (int h = 0; h < 4; h++) {
            ulonglong2 bv = bp[h];
            a0[2*h]=bv.x; a0[2*h+1]=bv.y;
            a1[2*h]=bv.x; a1[2*h+1]=bv.y;
        }
        #pragma unroll
        for (int d = 0; d < D; d++) {
            const ulonglong2* wr = (const ulonglong2*)(p + 272 + d * D);
            ulonglong2 wA = wr[0], wB = wr[1], wC = wr[2], wE = wr[3];
            unsigned long long u0 = splat2(x0[d]), u1 = splat2(x1[d]);
            ffma2(a0[0],u0,wA.x); ffma2(a1[0],u1,wA.x);
            ffma2(a0[1],u0,wA.y); ffma2(a1[1],u1,wA.y);
            ffma2(a0[2],u0,wB.x); ffma2(a1[2],u1,wB.x);
            ffma2(a0[3],u0,wB.y); ffma2(a1[3],u1,wB.y);
            ffma2(a0[4],u0,wC.x); ffma2(a1[4],u1,wC.x);
            ffma2(a0[5],u0,wC.y); ffma2(a1[5],u1,wC.y);
            ffma2(a0[6],u0,wE.x); ffma2(a1[6],u1,wE.x);
            ffma2(a0[7],u0,wE.y); ffma2(a1[7],u1,wE.y);
        }
    }

    // ---- Relu + store both rows (4x STG.128 each, fire-and-forget).
    {
        float4* o0 = (float4*)(out + grow * D);
        float4* o1 = (float4*)(out + (grow + 25) * D);
        #pragma unroll
        for (int q = 0; q < 4; q++) {
            float l0,h0,l1,h1, l2,h2,l3,h3;
            unpack2(a0[2*q],   l0, h0); unpack2(a0[2*q+1], l1, h1);
            unpack2(a1[2*q],   l2, h2); unpack2(a1[2*q+1], l3, h3);
            float4 v0 = { fmaxf(l0,0.f), fmaxf(h0,0.f), fmaxf(l1,0.f), fmaxf(h1,0.f) };
            float4 v1 = { fmaxf(l2,0.f), fmaxf(h2,0.f), fmaxf(l3,0.f), fmaxf(h3,0.f) };
            o0[q] = v0;
            o1[q] = v1;
        }
    }
}

extern "C" void kernel_launch(void* const* d_in, const int* in_sizes, int n_in,
                              void* d_out, int out_size) {
    const float* user_emb = (const float*)d_in[0];
    const float* item_emb = (const float*)d_in[1];
    float* out = (float*)d_out;
    const int B = in_sizes[1] / PARAMS;        // 16384
    can_kernel<<<B / WPC, THREADS>>>(user_emb, item_emb, out);
}